// round 4
// baseline (speedup 1.0000x reference)
#include <cuda_runtime.h>
#include <cstdint>

#define B_    16
#define CIN_  64
#define COUT_ 64
#define HH    256
#define WW    256
#define HW    (HH * WW)
#define EPSF  1e-8f

// Demodulated tf32 weights in exact mma-B fragment-consumption order:
// [b][tap][kk 0..7][i 0..3][lane 0..31][uint4]
// uint4 at (kk,i,lane{r=l>>2,p=l&3}) =
//   { B[co=i*16+r][k=p], B[co=i*16+r][k=p+4],
//     B[co=i*16+8+r][k=p], B[co=i*16+8+r][k=p+4] }   (k = ci - 8*kk)
__device__ __align__(16) float g_wt[B_ * 9 * 8 * 4 * 32 * 4];

__device__ __forceinline__ float f2tf32f(float x) {
    uint32_t r;
    asm("cvt.rna.tf32.f32 %0, %1;" : "=r"(r) : "f"(x));
    return __uint_as_float(r);
}

#define MMA_OP(d, a, b0, b1)                                                  \
    asm volatile(                                                             \
        "mma.sync.aligned.m16n8k8.row.col.f32.tf32.tf32.f32 "                 \
        "{%0,%1,%2,%3},{%4,%5,%6,%7},{%8,%9},{%0,%1,%2,%3};"                  \
        : "+f"((d)[0]), "+f"((d)[1]), "+f"((d)[2]), "+f"((d)[3])              \
        : "r"((a)[0]), "r"((a)[1]), "r"((a)[2]), "r"((a)[3]),                 \
          "r"(b0), "r"(b1))

// ---------------------------------------------------------------------------
// Kernel 1: modulate + demodulate + tf32-round + swizzle into fragment order
// grid (COUT, B), block CIN.
// ---------------------------------------------------------------------------
__global__ void modw_kernel(const float* __restrict__ w,
                            const float* __restrict__ y,
                            float* __restrict__ wt) {
    const int co = blockIdx.x;
    const int b  = blockIdx.y;
    const int ci = threadIdx.x;

    const float c  = 1.0f / 24.0f;               // (64*9)^-0.5
    const float yv = y[b * CIN_ + ci] * c;

    float v[9];
    float s = 0.0f;
    const float* wp = w + (co * CIN_ + ci) * 9;
#pragma unroll
    for (int t = 0; t < 9; t++) {
        v[t] = wp[t] * yv;
        s += v[t] * v[t];
    }
#pragma unroll
    for (int off = 16; off > 0; off >>= 1)
        s += __shfl_down_sync(0xffffffffu, s, off);
    __shared__ float ps[2];
    if ((ci & 31) == 0) ps[ci >> 5] = s;
    __syncthreads();
    const float d = rsqrtf(ps[0] + ps[1] + EPSF);

    const int kk   = ci >> 3;
    const int i    = co >> 4;
    const int lane = (co & 7) * 4 + (ci & 3);
    const int word = ((co >> 3) & 1) * 2 + ((ci >> 2) & 1);
#pragma unroll
    for (int t = 0; t < 9; t++) {
        const size_t idx =
            ((((size_t)(b * 9 + t) * 8 + kk) * 4 + i) * 32 + lane) * 4 + word;
        wt[idx] = f2tf32f(v[t] * d);
    }
}

// ---------------------------------------------------------------------------
// Kernel 2: tf32 mma.sync implicit-GEMM conv, warp tile M=32 x N=64, K-split.
// CTA: 128 px (2h x 64w) x 64 co, 8 warps.
//   (wid&3)  -> px group (32 px each)
//   (wid>>2) -> K group: kk 0-3 (ci 0-31) or kk 4-7 (ci 32-63) of every tap
// X tile staged once with halo: xs[64 ci][4 r][66 w], plane stride 264.
// Weights double-buffered per tap (16 KB each), fragment-order LDS.128.
// Epilogue: K-split reduction through smem (xs reused), group 1 stores.
// ---------------------------------------------------------------------------
#define XS_WORDS (64 * 264)        // 67.6 KB
#define WS_WORDS 4096              // 16 KB per tap buffer
#define DYN_SMEM ((XS_WORDS + 2 * WS_WORDS) * 4)

__global__ void __launch_bounds__(256, 2)
conv_mma_kernel(const float* __restrict__ X,
                const float* __restrict__ wt,
                float* __restrict__ out) {
    extern __shared__ __align__(16) float smem[];
    float* xs = smem;

    const int tid  = threadIdx.x;
    const int lane = tid & 31;
    const int wid  = tid >> 5;
    const int grp  = wid >> 2;           // K group
    const int px0  = (wid & 3) * 32;     // warp pixel base

    const int b  = blockIdx.z;
    const int h0 = blockIdx.y * 2;
    const int w0 = blockIdx.x * 64;

    // ---- stage X tile (once, covers all 9 taps), tf32-rounded ----
    {
        const float* Xb = X + (size_t)b * CIN_ * HW;
        for (int idx = tid; idx < XS_WORDS; idx += 256) {
            const int row66 = idx / 66;
            const int c     = idx - row66 * 66;
            if (c < 66) {
                const int ci = row66 >> 2;
                const int r  = row66 & 3;
                const int gh = h0 - 1 + r;
                const int gw = w0 - 1 + c;
                float v = 0.0f;
                if ((unsigned)gh < (unsigned)HH && (unsigned)gw < (unsigned)WW)
                    v = Xb[(size_t)ci * HW + gh * WW + gw];
                xs[(size_t)ci * 264 + (r * 66 + c)] = f2tf32f(v);
            }
        }
    }
    // ---- stage weights for tap 0 into buffer 0 ----
    {
        const float4* src = (const float4*)(wt + (size_t)(b * 9) * 4096);
        float4* dst = (float4*)(smem + XS_WORDS);
#pragma unroll
        for (int j = 0; j < 4; j++) dst[j * 256 + tid] = src[j * 256 + tid];
    }
    __syncthreads();

    float acc[2][8][4];
#pragma unroll
    for (int mt = 0; mt < 2; mt++)
#pragma unroll
        for (int nt = 0; nt < 8; nt++)
#pragma unroll
            for (int q = 0; q < 4; q++) acc[mt][nt][q] = 0.0f;

    for (int t = 0; t < 9; t++) {
        if (t < 8) {   // prefetch next tap's weights into the other buffer
            const float4* src = (const float4*)(wt + (size_t)(b * 9 + t + 1) * 4096);
            float4* dst = (float4*)(smem + XS_WORDS + ((t + 1) & 1) * WS_WORDS);
#pragma unroll
            for (int j = 0; j < 4; j++) dst[j * 256 + tid] = src[j * 256 + tid];
        }

        const int kh = t / 3, kw = t - kh * 3;
        // A base: ci plane = grp*32 + kkg*8 + (lane&3); +row; +col
        const float* abase = xs + (size_t)(grp * 32 + (lane & 3)) * 264
                           + ((px0 >> 6) + kh) * 66
                           + (px0 & 63) + (lane >> 2) + kw;
        // B base: this tap's buffer, this K group's half (4 slabs of 2KB)
        const char* bsm = (const char*)(smem + XS_WORDS + (t & 1) * WS_WORDS)
                        + grp * 8192 + lane * 16;

#pragma unroll
        for (int kkg = 0; kkg < 4; kkg++) {
            const float* ap = abase + kkg * (8 * 264);
            uint32_t a0[4], a1[4];
            a0[0] = __float_as_uint(ap[0]);
            a0[1] = __float_as_uint(ap[8]);
            a0[2] = __float_as_uint(ap[1056]);
            a0[3] = __float_as_uint(ap[1064]);
            a1[0] = __float_as_uint(ap[16]);
            a1[1] = __float_as_uint(ap[24]);
            a1[2] = __float_as_uint(ap[1072]);
            a1[3] = __float_as_uint(ap[1080]);

            const uint4* bp = (const uint4*)(bsm + kkg * 2048);
            {
                uint4 b0 = bp[0];     // co tiles 0,1
                uint4 b1 = bp[32];    // co tiles 2,3
                MMA_OP(acc[0][0], a0, b0.x, b0.y);
                MMA_OP(acc[1][0], a1, b0.x, b0.y);
                MMA_OP(acc[0][1], a0, b0.z, b0.w);
                MMA_OP(acc[1][1], a1, b0.z, b0.w);
                MMA_OP(acc[0][2], a0, b1.x, b1.y);
                MMA_OP(acc[1][2], a1, b1.x, b1.y);
                MMA_OP(acc[0][3], a0, b1.z, b1.w);
                MMA_OP(acc[1][3], a1, b1.z, b1.w);
            }
            {
                uint4 b2 = bp[64];    // co tiles 4,5
                uint4 b3 = bp[96];    // co tiles 6,7
                MMA_OP(acc[0][4], a0, b2.x, b2.y);
                MMA_OP(acc[1][4], a1, b2.x, b2.y);
                MMA_OP(acc[0][5], a0, b2.z, b2.w);
                MMA_OP(acc[1][5], a1, b2.z, b2.w);
                MMA_OP(acc[0][6], a0, b3.x, b3.y);
                MMA_OP(acc[1][6], a1, b3.x, b3.y);
                MMA_OP(acc[0][7], a0, b3.z, b3.w);
                MMA_OP(acc[1][7], a1, b3.z, b3.w);
            }
        }
        __syncthreads();   // protect weight buffer rotation
    }

    // ---- K-split reduction through smem (xs reused), then store ----
    float* rs = smem;
    const int ridx = ((wid & 3) * 32 + lane) * 68;   // pad 68 -> conflict-free
    if (grp == 0) {
#pragma unroll
        for (int mt = 0; mt < 2; mt++)
#pragma unroll
            for (int nt = 0; nt < 8; nt++)
                *(float4*)(rs + ridx + (mt * 8 + nt) * 4) =
                    *(const float4*)acc[mt][nt];
    }
    __syncthreads();
    if (grp == 1) {
#pragma unroll
        for (int mt = 0; mt < 2; mt++) {
            const int pxm  = px0 + mt * 16 + (lane >> 2);
            const int h    = h0 + (pxm >> 6);
            const int wcol = w0 + (pxm & 63);
            float* o0 = out + (size_t)b * COUT_ * HW + (size_t)h * WW + wcol;
#pragma unroll
            for (int nt = 0; nt < 8; nt++) {
                const float4 v = *(const float4*)(rs + ridx + (mt * 8 + nt) * 4);
                const int co = nt * 8 + 2 * (lane & 3);
                float* p = o0 + (size_t)co * HW;
                p[0]      = acc[mt][nt][0] + v.x;
                p[HW]     = acc[mt][nt][1] + v.y;
                p[8]      = acc[mt][nt][2] + v.z;
                p[HW + 8] = acc[mt][nt][3] + v.w;
            }
        }
    }
}

// ---------------------------------------------------------------------------
extern "C" void kernel_launch(void* const* d_in, const int* in_sizes, int n_in,
                              void* d_out, int out_size) {
    const float* X = (const float*)d_in[0];      // (16,64,256,256)
    const float* y = (const float*)d_in[1];      // (16,64)
    const float* w = (const float*)d_in[2];      // (64,64,3,3)
    float* out = (float*)d_out;                  // (16,64,256,256)

    float* wt;
    cudaGetSymbolAddress((void**)&wt, g_wt);

    cudaFuncSetAttribute(conv_mma_kernel,
                         cudaFuncAttributeMaxDynamicSharedMemorySize, DYN_SMEM);

    modw_kernel<<<dim3(COUT_, B_), CIN_>>>(w, y, wt);

    dim3 grid(WW / 64, HH / 2, B_);
    conv_mma_kernel<<<grid, 256, DYN_SMEM>>>(X, wt, out);
}

// round 5
// speedup vs baseline: 2.0043x; 2.0043x over previous
#include <cuda_runtime.h>
#include <cstdint>

#define B_    16
#define CIN_  64
#define COUT_ 64
#define HH    256
#define WW    256
#define HW    (HH * WW)
#define EPSF  1e-8f

// Demodulated tf32 weights in fragment-consumption order:
// [b][half 0..1][tap 0..8][kk 0..3][coh 0..1][ntp 0..1][lane 0..31][4 words]
// word layout per lane (p = lane&3, r = lane>>2):
//   { B[coh*32+ntp*16+r][k=p], B[..][k=p+4], B[coh*32+ntp*16+8+r][k=p], B[..][k=p+4] }
// where k = ci within the 8-wide kk block, ci = half*32 + kk*8 + k.
__device__ __align__(16) float g_wt[B_ * 2 * 9 * 4 * 2 * 2 * 32 * 4];

__device__ __forceinline__ float f2tf32f(float x) {
    uint32_t r;
    asm("cvt.rna.tf32.f32 %0, %1;" : "=r"(r) : "f"(x));
    return __uint_as_float(r);
}

#define MMA_OP(d, a, b0, b1)                                                  \
    asm volatile(                                                             \
        "mma.sync.aligned.m16n8k8.row.col.f32.tf32.tf32.f32 "                 \
        "{%0,%1,%2,%3},{%4,%5,%6,%7},{%8,%9},{%0,%1,%2,%3};"                  \
        : "+f"((d)[0]), "+f"((d)[1]), "+f"((d)[2]), "+f"((d)[3])              \
        : "r"((a)[0]), "r"((a)[1]), "r"((a)[2]), "r"((a)[3]),                 \
          "r"(b0), "r"(b1))

// ---------------------------------------------------------------------------
// Kernel 1: modulate + demodulate + tf32-round + swizzle into fragment order
// grid (COUT, B), block CIN.
// ---------------------------------------------------------------------------
__global__ void modw_kernel(const float* __restrict__ w,
                            const float* __restrict__ y,
                            float* __restrict__ wt) {
    const int co = blockIdx.x;
    const int b  = blockIdx.y;
    const int ci = threadIdx.x;

    const float c  = 1.0f / 24.0f;               // (64*9)^-0.5
    const float yv = y[b * CIN_ + ci] * c;

    float v[9];
    float s = 0.0f;
    const float* wp = w + (co * CIN_ + ci) * 9;
#pragma unroll
    for (int t = 0; t < 9; t++) {
        v[t] = wp[t] * yv;
        s += v[t] * v[t];
    }
#pragma unroll
    for (int off = 16; off > 0; off >>= 1)
        s += __shfl_down_sync(0xffffffffu, s, off);
    __shared__ float ps[2];
    if ((ci & 31) == 0) ps[ci >> 5] = s;
    __syncthreads();
    const float d = rsqrtf(ps[0] + ps[1] + EPSF);

    const int half = ci >> 5;
    const int kk   = (ci >> 3) & 3;
    const int k    = ci & 7;
    const int p    = k & 3;
    const int sgm  = k >> 2;
    const int coh  = co >> 5;
    const int cot  = (co >> 3) & 3;
    const int ntp  = cot >> 1;
    const int nto  = cot & 1;
    const int lane = (co & 7) * 4 + p;
    const int word = nto * 2 + sgm;

#pragma unroll
    for (int t = 0; t < 9; t++) {
        const size_t idx =
            ((((((size_t)((b * 2 + half) * 9 + t) * 4 + kk) * 2 + coh) * 2 + ntp)
              * 32 + lane) * 4) + word;
        wt[idx] = f2tf32f(v[t] * d);
    }
}

// ---------------------------------------------------------------------------
// Kernel 2: tf32 mma.sync implicit-GEMM conv, M32 x N32 warp tile,
// CIN split into 2 halves of 32 staged sequentially (smem 50KB -> 3 CTAs/SM).
// CTA: 128 px (2h x 64w) x 64 co, 8 warps: (wid&3)->px group, (wid>>2)->co half.
// xs[32 ci][4 r][66 w] plane stride 264; weights double-buffered 8KB/iter.
// ---------------------------------------------------------------------------
#define XS_WORDS (32 * 264)        // 33.8 KB
#define WS_WORDS 2048              // 8 KB per (half,tap) buffer
#define DYN_SMEM ((XS_WORDS + 2 * WS_WORDS) * 4)

__global__ void __launch_bounds__(256, 3)
conv_mma_kernel(const float* __restrict__ X,
                const float* __restrict__ wt,
                float* __restrict__ out) {
    extern __shared__ __align__(16) float smem[];
    float* xs = smem;
    float* ws = smem + XS_WORDS;

    const int tid  = threadIdx.x;
    const int lane = tid & 31;
    const int wid  = tid >> 5;
    const int coh  = wid >> 2;           // co half (0/1)
    const int px0  = (wid & 3) * 32;     // warp pixel base

    const int b  = blockIdx.z;
    const int h0 = blockIdx.y * 2;
    const int w0 = blockIdx.x * 64;

    const float* Xb = X + (size_t)b * CIN_ * HW;
    const float* Wb = wt + (size_t)b * 18 * WS_WORDS;

    // ---- stage weights for iteration 0 into buffer 0 ----
    {
        const float4* src = (const float4*)Wb;
        float4* dst = (float4*)ws;
#pragma unroll
        for (int j = 0; j < 2; j++) dst[j * 256 + tid] = src[j * 256 + tid];
    }

    float acc[2][4][4];
#pragma unroll
    for (int mt = 0; mt < 2; mt++)
#pragma unroll
        for (int nt = 0; nt < 4; nt++)
#pragma unroll
            for (int q = 0; q < 4; q++) acc[mt][nt][q] = 0.0f;

    int it = 0;
    for (int half = 0; half < 2; half++) {
        // ---- stage X half-tile (32 ci planes), tf32-rounded ----
        // (previous consumers are past: either kernel start or the sync at
        //  the end of the last tap of the previous half)
        if (half == 1) __syncthreads();  // ensure half-0 taps fully consumed xs
        {
            const float* Xh = Xb + (size_t)(half * 32) * HW;
            for (int idx = tid; idx < XS_WORDS; idx += 256) {
                const int row66 = idx / 66;
                const int c     = idx - row66 * 66;
                const int ci    = row66 >> 2;
                const int r     = row66 & 3;
                const int gh    = h0 - 1 + r;
                const int gw    = w0 - 1 + c;
                float v = 0.0f;
                if ((unsigned)gh < (unsigned)HH && (unsigned)gw < (unsigned)WW)
                    v = Xh[(size_t)ci * HW + gh * WW + gw];
                xs[idx] = f2tf32f(v);
            }
        }
        __syncthreads();

        for (int t = 0; t < 9; t++, it++) {
            // prefetch next iteration's weights into the other buffer
            if (it < 17) {
                const float4* src = (const float4*)(Wb + (size_t)(it + 1) * WS_WORDS);
                float4* dst = (float4*)(ws + ((it + 1) & 1) * WS_WORDS);
#pragma unroll
                for (int j = 0; j < 2; j++) dst[j * 256 + tid] = src[j * 256 + tid];
            }

            const int kh = t / 3, kw = t - kh * 3;
            const float* abase = xs + (size_t)(lane & 3) * 264
                               + ((px0 >> 6) + kh) * 66
                               + (px0 & 63) + (lane >> 2) + kw;
            const uint4* bbase = (const uint4*)(ws + (it & 1) * WS_WORDS
                                                + coh * 256) + lane;

#pragma unroll
            for (int kk = 0; kk < 4; kk++) {
                const float* ap = abase + kk * (8 * 264);
                uint32_t a0[4], a1[4];
                a0[0] = __float_as_uint(ap[0]);
                a0[1] = __float_as_uint(ap[8]);
                a0[2] = __float_as_uint(ap[1056]);
                a0[3] = __float_as_uint(ap[1064]);
                a1[0] = __float_as_uint(ap[16]);
                a1[1] = __float_as_uint(ap[24]);
                a1[2] = __float_as_uint(ap[1072]);
                a1[3] = __float_as_uint(ap[1080]);

                const uint4* bp = bbase + kk * 128;   // kk*512 words
                const uint4 b0 = bp[0];               // co tiles 0,1
                const uint4 b1 = bp[32];              // co tiles 2,3

                MMA_OP(acc[0][0], a0, b0.x, b0.y);
                MMA_OP(acc[1][0], a1, b0.x, b0.y);
                MMA_OP(acc[0][1], a0, b0.z, b0.w);
                MMA_OP(acc[1][1], a1, b0.z, b0.w);
                MMA_OP(acc[0][2], a0, b1.x, b1.y);
                MMA_OP(acc[1][2], a1, b1.x, b1.y);
                MMA_OP(acc[0][3], a0, b1.z, b1.w);
                MMA_OP(acc[1][3], a1, b1.z, b1.w);
            }
            __syncthreads();   // weight buffer rotation (and xs reuse gate)
        }
    }

    // ---- epilogue: direct store (full K accumulated per warp) ----
    const int co0 = coh * 32;
#pragma unroll
    for (int mt = 0; mt < 2; mt++) {
        const int pxm  = px0 + mt * 16 + (lane >> 2);
        const int h    = h0 + (pxm >> 6);
        const int wcol = w0 + (pxm & 63);
        float* o0 = out + (size_t)b * COUT_ * HW + (size_t)h * WW + wcol;
#pragma unroll
        for (int nt = 0; nt < 4; nt++) {
            const int co = co0 + nt * 8 + 2 * (lane & 3);
            float* p = o0 + (size_t)co * HW;
            p[0]      = acc[mt][nt][0];   // (px,    co)
            p[HW]     = acc[mt][nt][1];   // (px,    co+1)
            p[8]      = acc[mt][nt][2];   // (px+8,  co)
            p[HW + 8] = acc[mt][nt][3];   // (px+8,  co+1)
        }
    }
}

// ---------------------------------------------------------------------------
extern "C" void kernel_launch(void* const* d_in, const int* in_sizes, int n_in,
                              void* d_out, int out_size) {
    const float* X = (const float*)d_in[0];      // (16,64,256,256)
    const float* y = (const float*)d_in[1];      // (16,64)
    const float* w = (const float*)d_in[2];      // (64,64,3,3)
    float* out = (float*)d_out;                  // (16,64,256,256)

    float* wt;
    cudaGetSymbolAddress((void**)&wt, g_wt);

    cudaFuncSetAttribute(conv_mma_kernel,
                         cudaFuncAttributeMaxDynamicSharedMemorySize, DYN_SMEM);

    modw_kernel<<<dim3(COUT_, B_), CIN_>>>(w, y, wt);

    dim3 grid(WW / 64, HH / 2, B_);
    conv_mma_kernel<<<grid, 256, DYN_SMEM>>>(X, wt, out);
}

// round 6
// speedup vs baseline: 2.3776x; 1.1862x over previous
#include <cuda_runtime.h>
#include <cstdint>

#define B_    16
#define CIN_  64
#define COUT_ 64
#define HH    256
#define WW    256
#define HW    (HH * WW)
#define EPSF  1e-8f

// Demodulated tf32 weights in fragment-consumption order:
// [b][half 0..1][tap 0..8][kk 0..3][coh 0..1][ntp 0..1][lane 0..31][4 words]
// word layout per lane (p = lane&3, r = lane>>2):
//   { B[coh*32+ntp*16+r][k=p], B[..][k=p+4], B[coh*32+ntp*16+8+r][k=p], B[..][k=p+4] }
// where k = ci within the 8-wide kk block, ci = half*32 + kk*8 + k.
__device__ __align__(16) float g_wt[B_ * 2 * 9 * 4 * 2 * 2 * 32 * 4];

__device__ __forceinline__ float f2tf32f(float x) {
    uint32_t r;
    asm("cvt.rna.tf32.f32 %0, %1;" : "=r"(r) : "f"(x));
    return __uint_as_float(r);
}

#define MMA_OP(d, a, b0, b1)                                                  \
    asm volatile(                                                             \
        "mma.sync.aligned.m16n8k8.row.col.f32.tf32.tf32.f32 "                 \
        "{%0,%1,%2,%3},{%4,%5,%6,%7},{%8,%9},{%0,%1,%2,%3};"                  \
        : "+f"((d)[0]), "+f"((d)[1]), "+f"((d)[2]), "+f"((d)[3])              \
        : "r"((a)[0]), "r"((a)[1]), "r"((a)[2]), "r"((a)[3]),                 \
          "r"(b0), "r"(b1))

// ---------------------------------------------------------------------------
// Kernel 1: modulate + demodulate + tf32-round + swizzle into fragment order
// grid (COUT, B), block CIN.
// ---------------------------------------------------------------------------
__global__ void modw_kernel(const float* __restrict__ w,
                            const float* __restrict__ y,
                            float* __restrict__ wt) {
    const int co = blockIdx.x;
    const int b  = blockIdx.y;
    const int ci = threadIdx.x;

    const float c  = 1.0f / 24.0f;               // (64*9)^-0.5
    const float yv = y[b * CIN_ + ci] * c;

    float v[9];
    float s = 0.0f;
    const float* wp = w + (co * CIN_ + ci) * 9;
#pragma unroll
    for (int t = 0; t < 9; t++) {
        v[t] = wp[t] * yv;
        s += v[t] * v[t];
    }
#pragma unroll
    for (int off = 16; off > 0; off >>= 1)
        s += __shfl_down_sync(0xffffffffu, s, off);
    __shared__ float ps[2];
    if ((ci & 31) == 0) ps[ci >> 5] = s;
    __syncthreads();
    const float d = rsqrtf(ps[0] + ps[1] + EPSF);

    const int half = ci >> 5;
    const int kk   = (ci >> 3) & 3;
    const int k    = ci & 7;
    const int p    = k & 3;
    const int sgm  = k >> 2;
    const int coh  = co >> 5;
    const int cot  = (co >> 3) & 3;
    const int ntp  = cot >> 1;
    const int nto  = cot & 1;
    const int lane = (co & 7) * 4 + p;
    const int word = nto * 2 + sgm;

#pragma unroll
    for (int t = 0; t < 9; t++) {
        const size_t idx =
            ((((((size_t)((b * 2 + half) * 9 + t) * 4 + kk) * 2 + coh) * 2 + ntp)
              * 32 + lane) * 4) + word;
        wt[idx] = f2tf32f(v[t] * d);
    }
}

// ---------------------------------------------------------------------------
// Kernel 2: tf32 mma.sync implicit-GEMM conv, M32 x N32 warp tile.
// CIN split into 2 halves of 32 staged sequentially (smem 33.8KB).
// B operand loaded straight from gmem (fragment order, L1/L2-hit LDG.128):
// no weight smem, NO barriers inside the tap loop.
// CTA: 128 px (2h x 64w) x 64 co, 8 warps: (wid&3)->px group, (wid>>2)->co half.
// xs[32 ci][4 r][66 w], plane stride 264 (conflict-free A LDS).
// ---------------------------------------------------------------------------
#define XS_WORDS (32 * 264)        // 33.8 KB
#define DYN_SMEM (XS_WORDS * 4)

__global__ void __launch_bounds__(256, 3)
conv_mma_kernel(const float* __restrict__ X,
                const float* __restrict__ wt,
                float* __restrict__ out) {
    extern __shared__ __align__(16) float smem[];
    float* xs = smem;

    const int tid  = threadIdx.x;
    const int lane = tid & 31;
    const int wid  = tid >> 5;
    const int coh  = wid >> 2;           // co half (0/1)
    const int px0  = (wid & 3) * 32;     // warp pixel base

    const int b  = blockIdx.z;
    const int h0 = blockIdx.y * 2;
    const int w0 = blockIdx.x * 64;

    const float* Xb = X + (size_t)b * CIN_ * HW;
    // B fragment base for this warp: + coh block + lane (uint4 granularity)
    const uint4* WbF = (const uint4*)(wt + (size_t)b * 36864) + coh * 64 + lane;

    float acc[2][4][4];
#pragma unroll
    for (int mt = 0; mt < 2; mt++)
#pragma unroll
        for (int nt = 0; nt < 4; nt++)
#pragma unroll
            for (int q = 0; q < 4; q++) acc[mt][nt][q] = 0.0f;

#pragma unroll
    for (int half = 0; half < 2; half++) {
        // ---- stage X half-tile (32 ci planes), tf32-rounded ----
        if (half == 1) __syncthreads();  // all warps done consuming half 0
        {
            const float* Xh = Xb + (size_t)(half * 32) * HW;
            for (int idx = tid; idx < XS_WORDS; idx += 256) {
                const int row66 = idx / 66;
                const int c     = idx - row66 * 66;
                const int ci    = row66 >> 2;
                const int r     = row66 & 3;
                const int gh    = h0 - 1 + r;
                const int gw    = w0 - 1 + c;
                float v = 0.0f;
                if ((unsigned)gh < (unsigned)HH && (unsigned)gw < (unsigned)WW)
                    v = Xh[(size_t)ci * HW + gh * WW + gw];
                xs[idx] = f2tf32f(v);
            }
        }
        __syncthreads();

#pragma unroll
        for (int t = 0; t < 9; t++) {
            const int kh = t / 3, kw = t - kh * 3;
            const float* abase = xs + (size_t)(lane & 3) * 264
                               + ((px0 >> 6) + kh) * 66
                               + (px0 & 63) + (lane >> 2) + kw;
            // fragment stride per kk = 512 words = 128 uint4
            const uint4* bp = WbF + (size_t)((half * 9 + t) * 4) * 128;

#pragma unroll
            for (int kk = 0; kk < 4; kk++) {
                const uint4 b0 = __ldg(bp + kk * 128);        // co tiles 0,1
                const uint4 b1 = __ldg(bp + kk * 128 + 32);   // co tiles 2,3

                const float* ap = abase + kk * (8 * 264);
                uint32_t a0[4], a1[4];
                a0[0] = __float_as_uint(ap[0]);
                a0[1] = __float_as_uint(ap[8]);
                a0[2] = __float_as_uint(ap[1056]);
                a0[3] = __float_as_uint(ap[1064]);
                a1[0] = __float_as_uint(ap[16]);
                a1[1] = __float_as_uint(ap[24]);
                a1[2] = __float_as_uint(ap[1072]);
                a1[3] = __float_as_uint(ap[1080]);

                MMA_OP(acc[0][0], a0, b0.x, b0.y);
                MMA_OP(acc[1][0], a1, b0.x, b0.y);
                MMA_OP(acc[0][1], a0, b0.z, b0.w);
                MMA_OP(acc[1][1], a1, b0.z, b0.w);
                MMA_OP(acc[0][2], a0, b1.x, b1.y);
                MMA_OP(acc[1][2], a1, b1.x, b1.y);
                MMA_OP(acc[0][3], a0, b1.z, b1.w);
                MMA_OP(acc[1][3], a1, b1.z, b1.w);
            }
        }
    }

    // ---- epilogue: direct store (full K accumulated per warp) ----
    const int co0 = coh * 32;
#pragma unroll
    for (int mt = 0; mt < 2; mt++) {
        const int pxm  = px0 + mt * 16 + (lane >> 2);
        const int h    = h0 + (pxm >> 6);
        const int wcol = w0 + (pxm & 63);
        float* o0 = out + (size_t)b * COUT_ * HW + (size_t)h * WW + wcol;
#pragma unroll
        for (int nt = 0; nt < 4; nt++) {
            const int co = co0 + nt * 8 + 2 * (lane & 3);
            float* p = o0 + (size_t)co * HW;
            p[0]      = acc[mt][nt][0];   // (px,    co)
            p[HW]     = acc[mt][nt][1];   // (px,    co+1)
            p[8]      = acc[mt][nt][2];   // (px+8,  co)
            p[HW + 8] = acc[mt][nt][3];   // (px+8,  co+1)
        }
    }
}

// ---------------------------------------------------------------------------
extern "C" void kernel_launch(void* const* d_in, const int* in_sizes, int n_in,
                              void* d_out, int out_size) {
    const float* X = (const float*)d_in[0];      // (16,64,256,256)
    const float* y = (const float*)d_in[1];      // (16,64)
    const float* w = (const float*)d_in[2];      // (64,64,3,3)
    float* out = (float*)d_out;                  // (16,64,256,256)

    float* wt;
    cudaGetSymbolAddress((void**)&wt, g_wt);

    cudaFuncSetAttribute(conv_mma_kernel,
                         cudaFuncAttributeMaxDynamicSharedMemorySize, DYN_SMEM);

    modw_kernel<<<dim3(COUT_, B_), CIN_>>>(w, y, wt);

    dim3 grid(WW / 64, HH / 2, B_);
    conv_mma_kernel<<<grid, 256, DYN_SMEM>>>(X, wt, out);
}